// round 10
// baseline (speedup 1.0000x reference)
#include <cuda_runtime.h>
#include <cuda_fp16.h>
#include <cstdint>

#define NTOK 65536
#define MT 64
#define MAXTILE 1040

// byte offsets in dynamic smem
#define SM_X    0         // 64*68 half2 = 17408 B (pad 68 words/row)
#define SM_B    17408     // 2 x 65536 B chunk buffers
#define SM_PQ   148480    // P: 64x132 f32 (33792 B), Q follows
#define SM_BIAS 216064    // 1024 floats (both layers)
#define SM_TOK  220160    // 64 ints
#define SMEM_MAIN 220416

__device__ int g_cnt[9];          // zero at start; re-zeroed at end of k_main
__device__ int g_ntiles;
__device__ unsigned g_done;       // epoch counter (monotonic)
__device__ int g_tok[9 * NTOK];
__device__ int g_te[MAXTILE], g_ts[MAXTILE], g_tn[MAXTILE];
// fragment-ordered fp16 weights: per (l,e): 32768 words
// word = ks*4096 + g*1024 + nh*512 + ntp*128 + lane*4 + q   (ks = 0..7)
__device__ __align__(16) uint32_t g_Wf[18 * 32768];

__device__ __forceinline__ float tanha(float x) {
    float r; asm("tanh.approx.f32 %0,%1;" : "=f"(r) : "f"(x)); return r;
}
__device__ __forceinline__ float sigf(float v) {
    return fmaf(0.5f, tanha(0.5f * v), 0.5f);
}
__device__ __forceinline__ void mma16(float* c, const uint32_t* a, uint32_t b0, uint32_t b1) {
    asm volatile(
        "mma.sync.aligned.m16n8k16.row.col.f32.f16.f16.f32 "
        "{%0,%1,%2,%3},{%4,%5,%6,%7},{%8,%9},{%0,%1,%2,%3};"
        : "+f"(c[0]), "+f"(c[1]), "+f"(c[2]), "+f"(c[3])
        : "r"(a[0]), "r"(a[1]), "r"(a[2]), "r"(a[3]), "r"(b0), "r"(b1));
}
__device__ __forceinline__ uint32_t sptr(const void* p) {
    return (uint32_t)__cvta_generic_to_shared(p);
}
__device__ __forceinline__ void cpa16(uint32_t dst, const void* src) {
    asm volatile("cp.async.cg.shared.global [%0],[%1],16;" :: "r"(dst), "l"(src));
}
__device__ __forceinline__ uint32_t packh2(float a, float b) {
    __half2 h = __floats2half2_rn(a, b);
    return *(uint32_t*)&h;
}

// ---------------- prep: fused wprep (blocks 0..287) + hist/tiles (blocks 288..415) ----
__global__ void k_prep_all(const float* __restrict__ W, const int* __restrict__ pos) {
    int b = blockIdx.x;
    int tid = threadIdx.x;
    if (b < 288) {
        __shared__ float s[32 * 128];
        int m = b >> 2, kg = b & 3;
        int l = m / 36, g = (m / 9) % 4, e = m % 9;
        const float* src = W + (size_t)m * 16384 + kg * 4096;
        for (int i = tid; i < 4096; i += 512) s[i] = src[i];
        __syncthreads();
        uint32_t* dst = g_Wf + (size_t)(l * 9 + e) * 32768 + g * 1024;
        for (int i = tid; i < 2048; i += 512) {
            int ksl = i >> 10, nh = (i >> 9) & 1;
            int ntp = (i >> 7) & 3, lane = (i >> 2) & 31, q = i & 3;
            int tig = lane & 3, grp = lane >> 2, bsel = q & 1;
            int n = nh * 64 + (ntp * 2 + (q >> 1)) * 8 + grp;
            int k0l = ksl * 16 + bsel * 8 + 2 * tig;
            dst[(kg * 2 + ksl) * 4096 + nh * 512 + ntp * 128 + lane * 4 + q] =
                packh2(s[k0l * 128 + n], s[(k0l + 1) * 128 + n]);
        }
    } else {
        __shared__ int scnt[9], sbase[9];
        __shared__ int amlast;
        __shared__ int ts[10];
        int t = (b - 288) * 512 + tid;
        if (tid < 9) scnt[tid] = 0;
        int probe = t & 8191;
        int bad = (pos[2 * probe + 1] != 0);
        bad = __syncthreads_or(bad);
        int p = bad ? pos[t] : pos[2 * t];
        int e = p > 8 ? 8 : (p < 0 ? 0 : p);
        int my = atomicAdd(&scnt[e], 1);
        __syncthreads();
        if (tid < 9) sbase[tid] = atomicAdd(&g_cnt[tid], scnt[tid]);
        __syncthreads();
        g_tok[e * NTOK + sbase[e] + my] = t;
        __threadfence();
        __syncthreads();
        if (tid == 0) amlast = ((atomicAdd(&g_done, 1u) & 127u) == 127u);
        __syncthreads();
        if (amlast) {
            if (tid == 0) {
                ts[0] = 0;
                for (int ee = 0; ee < 9; ee++) ts[ee + 1] = ts[ee] + ((g_cnt[ee] + MT - 1) / MT);
                g_ntiles = ts[9];
            }
            __syncthreads();
            int n = ts[9];
            for (int tt = tid; tt < n; tt += 512) {
                int ee = 0;
                while (!(tt >= ts[ee] && tt < ts[ee + 1])) ee++;
                int s = (tt - ts[ee]) * MT;
                g_te[tt] = ee; g_ts[tt] = s;
                int rem = g_cnt[ee] - s;
                g_tn[tt] = rem < MT ? rem : MT;
            }
        }
    }
}

// ---------------- main: both layers per tile ----------------
// warp = (g in 4, mh2 in 2, nq in 4): two 16-row m-tiles, n32 column slice.
__global__ void __launch_bounds__(1024, 1)
k_main(const float* __restrict__ xin, const float* __restrict__ bs, float* __restrict__ out) {
    extern __shared__ __align__(16) char smc[];
    int bid = blockIdx.x;
    if (bid < g_ntiles) {
    int e = g_te[bid], s0 = g_ts[bid], nr = g_tn[bid];
    int tid = threadIdx.x, lane = tid & 31, w = tid >> 5;
    int g = w >> 3, mh2 = (w >> 2) & 1, nq = w & 3;
    int tig = lane & 3, grp = lane >> 2;

    uint32_t* Xs2 = (uint32_t*)smc;               // half2, stride 68 words/row
    float* P = (float*)(smc + SM_PQ);             // 64 x 132 fp32
    float* Q = P + 64 * 132;
    float* sbias = (float*)(smc + SM_BIAS);       // 1024 floats, both layers
    int* stok = (int*)(smc + SM_TOK);

    if (tid < MT) stok[tid] = (tid < nr) ? g_tok[e * NTOK + s0 + tid] : -1;
    sbias[tid] = bs[(((tid >> 9) * 4 + ((tid >> 7) & 3)) * 9 + e) * 128 + (tid & 127)];
    __syncthreads();
    for (int i = tid; i < MT * 32; i += 1024) {
        int r = i >> 5, c4 = i & 31;
        int t = stok[r];
        float4 v = (t >= 0) ? ((const float4*)xin)[(size_t)t * 32 + c4]
                            : make_float4(0.f, 0.f, 0.f, 0.f);
        Xs2[r * 68 + c4 * 2]     = packh2(v.x, v.y);
        Xs2[r * 68 + c4 * 2 + 1] = packh2(v.z, v.w);
    }

    // stage a layer's 128 KB of weights as two 64 KB cp.async groups
    #define STAGE2(lsel) do { \
        const uint4* _w = (const uint4*)(g_Wf + (size_t)((lsel) * 9 + e) * 32768); \
        uint32_t _d = sptr(smc + SM_B); \
        _Pragma("unroll") \
        for (int _ch = 0; _ch < 2; _ch++) { \
            _Pragma("unroll") \
            for (int _i = 0; _i < 4; _i++) \
                cpa16(_d + _ch * 65536 + (tid + _i * 1024) * 16, \
                      _w + _ch * 4096 + tid + _i * 1024); \
            asm volatile("cp.async.commit_group;"); \
        } \
    } while (0)

    STAGE2(0);

    for (int l = 0; l < 2; l++) {
        float acc[2][4][4];
        #pragma unroll
        for (int mt = 0; mt < 2; mt++)
            #pragma unroll
            for (int nt = 0; nt < 4; nt++)
                #pragma unroll
                for (int j = 0; j < 4; j++) acc[mt][nt][j] = 0.f;

        // this warp's B slice: gate g, n-half nh = nq>>1, ntp pair base (nq&1)*2
        #pragma unroll
        for (int ch = 0; ch < 2; ch++) {
            if (ch == 0) asm volatile("cp.async.wait_group 1;");
            else         asm volatile("cp.async.wait_group 0;");
            __syncthreads();
            const char* bsb = smc + SM_B + ch * 65536 + g * 4096 + (nq >> 1) * 2048
                              + (nq & 1) * 1024 + lane * 16;
            #pragma unroll
            for (int ksq = 0; ksq < 4; ksq++) {
                int ks = ch * 4 + ksq;
                uint32_t a0[4], a1[4];
                {
                    const uint32_t* xr = Xs2 + (mh2 * 32 + grp) * 68 + ks * 8 + tig;
                    a0[0] = xr[0]; a0[1] = xr[8 * 68]; a0[2] = xr[4]; a0[3] = xr[8 * 68 + 4];
                }
                {
                    const uint32_t* xr = Xs2 + (mh2 * 32 + 16 + grp) * 68 + ks * 8 + tig;
                    a1[0] = xr[0]; a1[1] = xr[8 * 68]; a1[2] = xr[4]; a1[3] = xr[8 * 68 + 4];
                }
                uint4 b0 = *(const uint4*)(bsb + ksq * 16384);
                uint4 b1 = *(const uint4*)(bsb + ksq * 16384 + 512);
                mma16(acc[0][0], a0, b0.x, b0.y);
                mma16(acc[1][0], a1, b0.x, b0.y);
                mma16(acc[0][1], a0, b0.z, b0.w);
                mma16(acc[1][1], a1, b0.z, b0.w);
                mma16(acc[0][2], a0, b1.x, b1.y);
                mma16(acc[1][2], a1, b1.x, b1.y);
                mma16(acc[0][3], a0, b1.z, b1.w);
                mma16(acc[1][3], a1, b1.z, b1.w);
            }
        }
        __syncthreads();             // all warps done reading B buffers
        if (l == 0) STAGE2(1);       // overlap layer-1 W staging with epilogue

        #define FRAG_LOOP(BODY) \
            _Pragma("unroll") for (int mt = 0; mt < 2; mt++) \
            _Pragma("unroll") for (int nt = 0; nt < 4; nt++) \
            _Pragma("unroll") for (int j = 0; j < 4; j++) { \
                int r = mh2 * 32 + mt * 16 + grp + ((j >> 1) << 3); \
                int c = nq * 32 + nt * 8 + tig * 2 + (j & 1); \
                float v = acc[mt][nt][j] + sbias[l * 512 + g * 128 + c]; \
                (void)v; BODY }

        if (g == 0) {
            FRAG_LOOP(
                uint32_t xp = Xs2[r * 68 + (c >> 1)];
                __half2 xh = *(__half2*)&xp;
                float xv = (c & 1) ? __half2float(__high2half(xh)) : __half2float(__low2half(xh));
                P[r * 132 + c] = xv * sigf(v);
            )
        } else if (g == 1) {
            FRAG_LOOP( Q[r * 132 + c] = tanha(v); )
        }
        __syncthreads();
        if (g == 2) {
            FRAG_LOOP( P[r * 132 + c] += Q[r * 132 + c] * sigf(v); )
        }
        __syncthreads();
        if (g == 3) {
            FRAG_LOOP( Q[r * 132 + c] = tanha(P[r * 132 + c]) * sigf(v); )
        }
        __syncthreads();
        if (l == 0) {
            for (int i = tid; i < MT * 64; i += 1024) {
                int r = i >> 6, p2 = i & 63;
                Xs2[r * 68 + p2] = packh2(Q[r * 132 + 2 * p2], Q[r * 132 + 2 * p2 + 1]);
            }
            __syncthreads();
        } else {
            for (int i = tid; i < MT * 32; i += 1024) {
                int r = i >> 5, c4 = i & 31;
                int t = stok[r];
                if (t >= 0)
                    ((float4*)out)[(size_t)t * 32 + c4] = *(float4*)&Q[r * 132 + c4 * 4];
            }
        }
        #undef FRAG_LOOP
    }
    #undef STAGE2
    }
    // reset histogram for next launch (graph replay); this block's work is done
    if (blockIdx.x == 0 && threadIdx.x < 9) g_cnt[threadIdx.x] = 0;
}

extern "C" void kernel_launch(void* const* d_in, const int* in_sizes, int n_in,
                              void* d_out, int out_size) {
    const int* pos = (const int*)d_in[0];
    const float* x = (const float*)d_in[1];
    const float* W = (const float*)d_in[2];
    const float* b = (const float*)d_in[3];
    float* out = (float*)d_out;
    (void)in_sizes; (void)n_in; (void)out_size;
    cudaFuncSetAttribute(k_main, cudaFuncAttributeMaxDynamicSharedMemorySize, SMEM_MAIN);
    k_prep_all<<<416, 512>>>(W, pos);
    k_main<<<MAXTILE, 1024, SMEM_MAIN>>>(x, b, out);
}

// round 11
// speedup vs baseline: 1.8622x; 1.8622x over previous
#include <cuda_runtime.h>
#include <cuda_fp16.h>
#include <cstdint>

#define NTOK 65536
#define MT 64
#define MAXTILE 1040

// byte offsets in dynamic smem
#define SM_X    0         // 64*68 half2 words = 17408 B
#define SM_B    17408     // 2 x 65536 B chunk buffers
#define SM_PQ   148480    // Ph: 64x68 half2 (17408 B), Qh follows
#define SM_BIAS 183296    // 1024 floats (both layers)
#define SM_TOK  187392    // 64 ints
#define SMEM_MAIN 187648

__device__ int g_cnt[9];          // zero at start (BSS); re-zeroed at end of k_main
__device__ int g_ntiles;
__device__ unsigned g_done;       // epoch counter (monotonic)
__device__ int g_tok[9 * NTOK];
__device__ int g_te[MAXTILE], g_ts[MAXTILE], g_tn[MAXTILE];
// fragment-ordered fp16 weights: per (l,e): 32768 words
// word = ks*4096 + g*1024 + nh*512 + ntp*128 + lane*4 + q   (ks = 0..7)
__device__ __align__(16) uint32_t g_Wf[18 * 32768];

__device__ __forceinline__ float tanha(float x) {
    float r; asm("tanh.approx.f32 %0,%1;" : "=f"(r) : "f"(x)); return r;
}
__device__ __forceinline__ float sigf(float v) {
    return fmaf(0.5f, tanha(0.5f * v), 0.5f);
}
__device__ __forceinline__ void mma16(float* c, const uint32_t* a, uint32_t b0, uint32_t b1) {
    asm volatile(
        "mma.sync.aligned.m16n8k16.row.col.f32.f16.f16.f32 "
        "{%0,%1,%2,%3},{%4,%5,%6,%7},{%8,%9},{%0,%1,%2,%3};"
        : "+f"(c[0]), "+f"(c[1]), "+f"(c[2]), "+f"(c[3])
        : "r"(a[0]), "r"(a[1]), "r"(a[2]), "r"(a[3]), "r"(b0), "r"(b1));
}
__device__ __forceinline__ uint32_t sptr(const void* p) {
    return (uint32_t)__cvta_generic_to_shared(p);
}
__device__ __forceinline__ void cpa16(uint32_t dst, const void* src) {
    asm volatile("cp.async.cg.shared.global [%0],[%1],16;" :: "r"(dst), "l"(src));
}
__device__ __forceinline__ uint32_t packh2(float a, float b) {
    __half2 h = __floats2half2_rn(a, b);
    return *(uint32_t*)&h;
}

// ---------------- prep: fused wprep (blocks 0..287) + hist/tiles (blocks 288..415) ----
__global__ void k_prep_all(const float* __restrict__ W, const int* __restrict__ pos) {
    int b = blockIdx.x;
    int tid = threadIdx.x;
    if (b < 288) {
        __shared__ float s[32 * 128];
        int m = b >> 2, kg = b & 3;
        int l = m / 36, g = (m / 9) % 4, e = m % 9;
        const float* src = W + (size_t)m * 16384 + kg * 4096;
        for (int i = tid; i < 4096; i += 512) s[i] = src[i];
        __syncthreads();
        uint32_t* dst = g_Wf + (size_t)(l * 9 + e) * 32768 + g * 1024;
        for (int i = tid; i < 2048; i += 512) {
            int ksl = i >> 10, nh = (i >> 9) & 1;
            int ntp = (i >> 7) & 3, lane = (i >> 2) & 31, q = i & 3;
            int tig = lane & 3, grp = lane >> 2, bsel = q & 1;
            int n = nh * 64 + (ntp * 2 + (q >> 1)) * 8 + grp;
            int k0l = ksl * 16 + bsel * 8 + 2 * tig;
            dst[(kg * 2 + ksl) * 4096 + nh * 512 + ntp * 128 + lane * 4 + q] =
                packh2(s[k0l * 128 + n], s[(k0l + 1) * 128 + n]);
        }
    } else {
        __shared__ int scnt[9], sbase[9];
        __shared__ int amlast;
        __shared__ int ts[10];
        int t = (b - 288) * 512 + tid;
        if (tid < 9) scnt[tid] = 0;
        int probe = t & 8191;
        int bad = (pos[2 * probe + 1] != 0);
        bad = __syncthreads_or(bad);
        int p = bad ? pos[t] : pos[2 * t];
        int e = p > 8 ? 8 : (p < 0 ? 0 : p);
        int my = atomicAdd(&scnt[e], 1);
        __syncthreads();
        if (tid < 9) sbase[tid] = atomicAdd(&g_cnt[tid], scnt[tid]);
        __syncthreads();
        g_tok[e * NTOK + sbase[e] + my] = t;
        __threadfence();
        __syncthreads();
        if (tid == 0) amlast = ((atomicAdd(&g_done, 1u) & 127u) == 127u);
        __syncthreads();
        if (amlast) {
            if (tid == 0) {
                ts[0] = 0;
                for (int ee = 0; ee < 9; ee++) ts[ee + 1] = ts[ee] + ((g_cnt[ee] + MT - 1) / MT);
                g_ntiles = ts[9];
            }
            __syncthreads();
            int n = ts[9];
            for (int tt = tid; tt < n; tt += 512) {
                int ee = 0;
                while (!(tt >= ts[ee] && tt < ts[ee + 1])) ee++;
                int s = (tt - ts[ee]) * MT;
                g_te[tt] = ee; g_ts[tt] = s;
                int rem = g_cnt[ee] - s;
                g_tn[tt] = rem < MT ? rem : MT;
            }
        }
    }
}

// ---------------- main: both layers per tile (R7 mainloop, half2 epilogue) ----------------
__global__ void __launch_bounds__(1024, 1)
k_main(const float* __restrict__ xin, const float* __restrict__ bs, float* __restrict__ out) {
    extern __shared__ __align__(16) char smc[];
    int bid = blockIdx.x;
    if (bid < g_ntiles) {
    int e = g_te[bid], s0 = g_ts[bid], nr = g_tn[bid];
    int tid = threadIdx.x, lane = tid & 31, w = tid >> 5;
    int g = w >> 3, mh = (w >> 1) & 3, nh = w & 1;
    int tig = lane & 3, grp = lane >> 2;

    uint32_t* Xs2 = (uint32_t*)smc;               // half2, stride 68 words/row
    uint32_t* Ph = (uint32_t*)(smc + SM_PQ);      // half2 pairs, stride 68
    uint32_t* Qh = Ph + 4352;
    float* sbias = (float*)(smc + SM_BIAS);       // 1024 floats, both layers
    int* stok = (int*)(smc + SM_TOK);

    if (tid < MT) stok[tid] = (tid < nr) ? g_tok[e * NTOK + s0 + tid] : -1;
    sbias[tid] = bs[(((tid >> 9) * 4 + ((tid >> 7) & 3)) * 9 + e) * 128 + (tid & 127)];
    __syncthreads();
    for (int i = tid; i < MT * 32; i += 1024) {
        int r = i >> 5, c4 = i & 31;
        int t = stok[r];
        float4 v = (t >= 0) ? ((const float4*)xin)[(size_t)t * 32 + c4]
                            : make_float4(0.f, 0.f, 0.f, 0.f);
        Xs2[r * 68 + c4 * 2]     = packh2(v.x, v.y);
        Xs2[r * 68 + c4 * 2 + 1] = packh2(v.z, v.w);
    }

    // stage a layer's 128 KB of weights as two 64 KB cp.async groups
    #define STAGE2(lsel) do { \
        const uint4* _w = (const uint4*)(g_Wf + (size_t)((lsel) * 9 + e) * 32768); \
        uint32_t _d = sptr(smc + SM_B); \
        _Pragma("unroll") \
        for (int _ch = 0; _ch < 2; _ch++) { \
            _Pragma("unroll") \
            for (int _i = 0; _i < 4; _i++) \
                cpa16(_d + _ch * 65536 + (tid + _i * 1024) * 16, \
                      _w + _ch * 4096 + tid + _i * 1024); \
            asm volatile("cp.async.commit_group;"); \
        } \
    } while (0)

    STAGE2(0);

    for (int l = 0; l < 2; l++) {
        float acc[8][4];
        #pragma unroll
        for (int nt = 0; nt < 8; nt++)
            #pragma unroll
            for (int j = 0; j < 4; j++) acc[nt][j] = 0.f;

        #pragma unroll
        for (int ch = 0; ch < 2; ch++) {
            if (ch == 0) asm volatile("cp.async.wait_group 1;");
            else         asm volatile("cp.async.wait_group 0;");
            __syncthreads();
            const char* bsb = smc + SM_B + ch * 65536 + g * 4096 + nh * 2048 + lane * 16;
            #pragma unroll
            for (int ksq = 0; ksq < 4; ksq++) {
                int ks = ch * 4 + ksq;
                const uint32_t* xr = Xs2 + (mh * 16 + grp) * 68 + ks * 8 + tig;
                uint32_t a[4];
                a[0] = xr[0]; a[1] = xr[8 * 68]; a[2] = xr[4]; a[3] = xr[8 * 68 + 4];
                #pragma unroll
                for (int ntp = 0; ntp < 4; ntp++) {
                    uint4 b = *(const uint4*)(bsb + ksq * 16384 + ntp * 512);
                    mma16(acc[2 * ntp],     a, b.x, b.y);
                    mma16(acc[2 * ntp + 1], a, b.z, b.w);
                }
            }
        }
        __syncthreads();             // all warps done reading B buffers
        if (l == 0) STAGE2(1);       // overlap layer-1 W staging with epilogue

        // ---- half2 epilogue: pair index cp covers columns 2cp, 2cp+1 ----
        const float* sb = sbias + l * 512 + g * 128;
        #define EPI_LOOP(BODY) \
            _Pragma("unroll") for (int nt = 0; nt < 8; nt++) \
            _Pragma("unroll") for (int jh = 0; jh < 2; jh++) { \
                int r = mh * 16 + grp + jh * 8; \
                int cp = nh * 32 + nt * 4 + tig; \
                float va = acc[nt][jh * 2]     + sb[2 * cp]; \
                float vb = acc[nt][jh * 2 + 1] + sb[2 * cp + 1]; \
                (void)r; (void)cp; (void)va; (void)vb; BODY }

        if (g == 0) {
            EPI_LOOP(
                uint32_t xp = Xs2[r * 68 + cp];
                __half2 xh = *(__half2*)&xp;
                Ph[r * 68 + cp] = packh2(__low2float(xh) * sigf(va),
                                         __high2float(xh) * sigf(vb));
            )
        } else if (g == 1) {
            EPI_LOOP( Qh[r * 68 + cp] = packh2(tanha(va), tanha(vb)); )
        }
        __syncthreads();
        if (g == 2) {
            EPI_LOOP(
                uint32_t pw = Ph[r * 68 + cp];
                uint32_t qw = Qh[r * 68 + cp];
                __half2 phh = *(__half2*)&pw;
                __half2 qhh = *(__half2*)&qw;
                float p0 = fmaf(__low2float(qhh),  sigf(va), __low2float(phh));
                float p1 = fmaf(__high2float(qhh), sigf(vb), __high2float(phh));
                Ph[r * 68 + cp] = packh2(p0, p1);
            )
        }
        __syncthreads();
        if (g == 3) {
            if (l == 0) {
                EPI_LOOP(
                    uint32_t pw = Ph[r * 68 + cp];
                    __half2 phh = *(__half2*)&pw;
                    Xs2[r * 68 + cp] = packh2(tanha(__low2float(phh))  * sigf(va),
                                              tanha(__high2float(phh)) * sigf(vb));
                )
            } else {
                EPI_LOOP(
                    uint32_t pw = Ph[r * 68 + cp];
                    __half2 phh = *(__half2*)&pw;
                    int tk = stok[r];
                    if (tk >= 0)
                        ((float2*)out)[(size_t)tk * 64 + cp] =
                            make_float2(tanha(__low2float(phh))  * sigf(va),
                                        tanha(__high2float(phh)) * sigf(vb));
                )
            }
        }
        #undef EPI_LOOP
        // no trailing sync needed: next layer's ch0 wait+sync orders Xs2 writes
    }
    #undef STAGE2
    }
    // reset histogram for next launch (graph replay)
    if (blockIdx.x == 0 && threadIdx.x < 9) g_cnt[threadIdx.x] = 0;
}

extern "C" void kernel_launch(void* const* d_in, const int* in_sizes, int n_in,
                              void* d_out, int out_size) {
    const int* pos = (const int*)d_in[0];
    const float* x = (const float*)d_in[1];
    const float* W = (const float*)d_in[2];
    const float* b = (const float*)d_in[3];
    float* out = (float*)d_out;
    (void)in_sizes; (void)n_in; (void)out_size;
    cudaFuncSetAttribute(k_main, cudaFuncAttributeMaxDynamicSharedMemorySize, SMEM_MAIN);
    k_prep_all<<<416, 512>>>(W, pos);
    k_main<<<MAXTILE, 1024, SMEM_MAIN>>>(x, b, out);
}

// round 12
// speedup vs baseline: 1.9061x; 1.0236x over previous
#include <cuda_runtime.h>
#include <cuda_fp16.h>
#include <cstdint>

#define NTOK 65536
#define MT 64
#define MAXTILE 1040

// byte offsets in dynamic smem
#define SM_X    0         // 64*68 half2 words = 17408 B
#define SM_B    17408     // 2 x 65536 B chunk buffers
#define SM_PQ   148480    // Ph: 64x68 half2 (17408 B), Qh follows
#define SM_BIAS 183296    // 1024 floats (both layers)
#define SM_TOK  187392    // 64 ints
#define SMEM_MAIN 187648

__device__ int g_cnt[9];          // zero at start (BSS); re-zeroed at end of k_main
__device__ int g_ntiles;
__device__ unsigned g_done;       // epoch counter (monotonic)
__device__ int g_tok[9 * NTOK];
__device__ int g_te[MAXTILE], g_ts[MAXTILE], g_tn[MAXTILE];
// fragment-ordered fp16 weights: per (l,e): 32768 words
// word = ks*4096 + g*1024 + nh*512 + ntp*128 + lane*4 + q   (ks = 0..7)
__device__ __align__(16) uint32_t g_Wf[18 * 32768];

__device__ __forceinline__ float tanha(float x) {
    float r; asm("tanh.approx.f32 %0,%1;" : "=f"(r) : "f"(x)); return r;
}
__device__ __forceinline__ float sigf(float v) {
    return fmaf(0.5f, tanha(0.5f * v), 0.5f);
}
__device__ __forceinline__ void mma16(float* c, const uint32_t* a, uint32_t b0, uint32_t b1) {
    asm volatile(
        "mma.sync.aligned.m16n8k16.row.col.f32.f16.f16.f32 "
        "{%0,%1,%2,%3},{%4,%5,%6,%7},{%8,%9},{%0,%1,%2,%3};"
        : "+f"(c[0]), "+f"(c[1]), "+f"(c[2]), "+f"(c[3])
        : "r"(a[0]), "r"(a[1]), "r"(a[2]), "r"(a[3]), "r"(b0), "r"(b1));
}
__device__ __forceinline__ uint32_t sptr(const void* p) {
    return (uint32_t)__cvta_generic_to_shared(p);
}
__device__ __forceinline__ void cpa16(uint32_t dst, const void* src) {
    asm volatile("cp.async.cg.shared.global [%0],[%1],16;" :: "r"(dst), "l"(src));
}
__device__ __forceinline__ uint32_t packh2(float a, float b) {
    __half2 h = __floats2half2_rn(a, b);
    return *(uint32_t*)&h;
}
// sequenced 128-bit shared load (volatile: cannot be hoisted across volatile MMAs)
__device__ __forceinline__ uint4 lds128(uint32_t addr) {
    uint4 v;
    asm volatile("ld.shared.v4.b32 {%0,%1,%2,%3},[%4];"
        : "=r"(v.x), "=r"(v.y), "=r"(v.z), "=r"(v.w) : "r"(addr));
    return v;
}

// ---------------- prep: fused wprep (blocks 0..287) + hist/tiles (blocks 288..415) ----
__global__ void k_prep_all(const float* __restrict__ W, const int* __restrict__ pos) {
    int b = blockIdx.x;
    int tid = threadIdx.x;
    if (b < 288) {
        __shared__ float s[32 * 128];
        int m = b >> 2, kg = b & 3;
        int l = m / 36, g = (m / 9) % 4, e = m % 9;
        const float* src = W + (size_t)m * 16384 + kg * 4096;
        for (int i = tid; i < 4096; i += 512) s[i] = src[i];
        __syncthreads();
        uint32_t* dst = g_Wf + (size_t)(l * 9 + e) * 32768 + g * 1024;
        for (int i = tid; i < 2048; i += 512) {
            int ksl = i >> 10, nh = (i >> 9) & 1;
            int ntp = (i >> 7) & 3, lane = (i >> 2) & 31, q = i & 3;
            int tig = lane & 3, grp = lane >> 2, bsel = q & 1;
            int n = nh * 64 + (ntp * 2 + (q >> 1)) * 8 + grp;
            int k0l = ksl * 16 + bsel * 8 + 2 * tig;
            dst[(kg * 2 + ksl) * 4096 + nh * 512 + ntp * 128 + lane * 4 + q] =
                packh2(s[k0l * 128 + n], s[(k0l + 1) * 128 + n]);
        }
    } else {
        __shared__ int scnt[9], sbase[9];
        __shared__ int amlast;
        __shared__ int ts[10];
        int t = (b - 288) * 512 + tid;
        if (tid < 9) scnt[tid] = 0;
        int probe = t & 8191;
        int bad = (pos[2 * probe + 1] != 0);
        bad = __syncthreads_or(bad);
        int p = bad ? pos[t] : pos[2 * t];
        int e = p > 8 ? 8 : (p < 0 ? 0 : p);
        int my = atomicAdd(&scnt[e], 1);
        __syncthreads();
        if (tid < 9) sbase[tid] = atomicAdd(&g_cnt[tid], scnt[tid]);
        __syncthreads();
        g_tok[e * NTOK + sbase[e] + my] = t;
        __threadfence();
        __syncthreads();
        if (tid == 0) amlast = ((atomicAdd(&g_done, 1u) & 127u) == 127u);
        __syncthreads();
        if (amlast) {
            if (tid == 0) {
                ts[0] = 0;
                for (int ee = 0; ee < 9; ee++) ts[ee + 1] = ts[ee] + ((g_cnt[ee] + MT - 1) / MT);
                g_ntiles = ts[9];
            }
            __syncthreads();
            int n = ts[9];
            for (int tt = tid; tt < n; tt += 512) {
                int ee = 0;
                while (!(tt >= ts[ee] && tt < ts[ee + 1])) ee++;
                int s = (tt - ts[ee]) * MT;
                g_te[tt] = ee; g_ts[tt] = s;
                int rem = g_cnt[ee] - s;
                g_tn[tt] = rem < MT ? rem : MT;
            }
        }
    }
}

// ---------------- main: both layers per tile ----------------
// warp = (g in 4, mh2 in 2, nq in 4): m32 x n32 per warp; each B uint4 feeds 4 MMAs.
__global__ void __launch_bounds__(1024, 1)
k_main(const float* __restrict__ xin, const float* __restrict__ bs, float* __restrict__ out) {
    extern __shared__ __align__(16) char smc[];
    int bid = blockIdx.x;
    if (bid < g_ntiles) {
    int e = g_te[bid], s0 = g_ts[bid], nr = g_tn[bid];
    int tid = threadIdx.x, lane = tid & 31, w = tid >> 5;
    int g = w >> 3, mh2 = (w >> 2) & 1, nq = w & 3;
    int tig = lane & 3, grp = lane >> 2;

    uint32_t* Xs2 = (uint32_t*)smc;               // half2, stride 68 words/row
    uint32_t* Ph = (uint32_t*)(smc + SM_PQ);      // half2 pairs, stride 68
    uint32_t* Qh = Ph + 4352;
    float* sbias = (float*)(smc + SM_BIAS);       // 1024 floats, both layers
    int* stok = (int*)(smc + SM_TOK);

    if (tid < MT) stok[tid] = (tid < nr) ? g_tok[e * NTOK + s0 + tid] : -1;
    sbias[tid] = bs[(((tid >> 9) * 4 + ((tid >> 7) & 3)) * 9 + e) * 128 + (tid & 127)];
    __syncthreads();
    for (int i = tid; i < MT * 32; i += 1024) {
        int r = i >> 5, c4 = i & 31;
        int t = stok[r];
        float4 v = (t >= 0) ? ((const float4*)xin)[(size_t)t * 32 + c4]
                            : make_float4(0.f, 0.f, 0.f, 0.f);
        Xs2[r * 68 + c4 * 2]     = packh2(v.x, v.y);
        Xs2[r * 68 + c4 * 2 + 1] = packh2(v.z, v.w);
    }

    // stage a layer's 128 KB of weights as two 64 KB cp.async groups
    #define STAGE2(lsel) do { \
        const uint4* _w = (const uint4*)(g_Wf + (size_t)((lsel) * 9 + e) * 32768); \
        uint32_t _d = sptr(smc + SM_B); \
        _Pragma("unroll") \
        for (int _ch = 0; _ch < 2; _ch++) { \
            _Pragma("unroll") \
            for (int _i = 0; _i < 4; _i++) \
                cpa16(_d + _ch * 65536 + (tid + _i * 1024) * 16, \
                      _w + _ch * 4096 + tid + _i * 1024); \
            asm volatile("cp.async.commit_group;"); \
        } \
    } while (0)

    STAGE2(0);

    for (int l = 0; l < 2; l++) {
        float acc[2][4][4];
        #pragma unroll
        for (int mt = 0; mt < 2; mt++)
            #pragma unroll
            for (int nt = 0; nt < 4; nt++)
                #pragma unroll
                for (int j = 0; j < 4; j++) acc[mt][nt][j] = 0.f;

        #pragma unroll
        for (int ch = 0; ch < 2; ch++) {
            if (ch == 0) asm volatile("cp.async.wait_group 1;");
            else         asm volatile("cp.async.wait_group 0;");
            __syncthreads();
            // warp's B slice: gate g, nh = nq>>1, wprep-ntp pair = (nq&1)*2 + {0,1}
            uint32_t bsb = sptr(smc) + SM_B + ch * 65536 + g * 4096 + (nq >> 1) * 2048
                           + (nq & 1) * 1024 + lane * 16;
            #pragma unroll
            for (int ksq = 0; ksq < 4; ksq++) {
                int ks = ch * 4 + ksq;
                const uint32_t* xr0 = Xs2 + (mh2 * 32 + grp) * 68 + ks * 8 + tig;
                uint32_t a0[4], a1[4];
                a0[0] = xr0[0]; a0[1] = xr0[8 * 68]; a0[2] = xr0[4]; a0[3] = xr0[8 * 68 + 4];
                const uint32_t* xr1 = xr0 + 16 * 68;
                a1[0] = xr1[0]; a1[1] = xr1[8 * 68]; a1[2] = xr1[4]; a1[3] = xr1[8 * 68 + 4];
                #pragma unroll
                for (int ntp = 0; ntp < 2; ntp++) {
                    uint4 b = lds128(bsb + ksq * 16384 + ntp * 512);
                    mma16(acc[0][2 * ntp],     a0, b.x, b.y);
                    mma16(acc[1][2 * ntp],     a1, b.x, b.y);
                    mma16(acc[0][2 * ntp + 1], a0, b.z, b.w);
                    mma16(acc[1][2 * ntp + 1], a1, b.z, b.w);
                }
            }
        }
        __syncthreads();             // all warps done reading B buffers
        if (l == 0) STAGE2(1);       // overlap layer-1 W staging with epilogue

        // ---- half2 epilogue: pair cp covers columns 2cp, 2cp+1 ----
        const float* sb = sbias + l * 512 + g * 128;
        #define EPI_LOOP(BODY) \
            _Pragma("unroll") for (int mt = 0; mt < 2; mt++) \
            _Pragma("unroll") for (int nt = 0; nt < 4; nt++) \
            _Pragma("unroll") for (int jh = 0; jh < 2; jh++) { \
                int r = mh2 * 32 + mt * 16 + grp + jh * 8; \
                int cp = nq * 16 + nt * 4 + tig; \
                float va = acc[mt][nt][jh * 2]     + sb[2 * cp]; \
                float vb = acc[mt][nt][jh * 2 + 1] + sb[2 * cp + 1]; \
                (void)r; (void)cp; (void)va; (void)vb; BODY }

        if (g == 0) {
            EPI_LOOP(
                uint32_t xp = Xs2[r * 68 + cp];
                __half2 xh = *(__half2*)&xp;
                Ph[r * 68 + cp] = packh2(__low2float(xh) * sigf(va),
                                         __high2float(xh) * sigf(vb));
            )
        } else if (g == 1) {
            EPI_LOOP( Qh[r * 68 + cp] = packh2(tanha(va), tanha(vb)); )
        }
        __syncthreads();
        if (g == 2) {
            EPI_LOOP(
                uint32_t pw = Ph[r * 68 + cp];
                uint32_t qw = Qh[r * 68 + cp];
                __half2 phh = *(__half2*)&pw;
                __half2 qhh = *(__half2*)&qw;
                float p0 = fmaf(__low2float(qhh),  sigf(va), __low2float(phh));
                float p1 = fmaf(__high2float(qhh), sigf(vb), __high2float(phh));
                Ph[r * 68 + cp] = packh2(p0, p1);
            )
        }
        __syncthreads();
        if (g == 3) {
            if (l == 0) {
                EPI_LOOP(
                    uint32_t pw = Ph[r * 68 + cp];
                    __half2 phh = *(__half2*)&pw;
                    Xs2[r * 68 + cp] = packh2(tanha(__low2float(phh))  * sigf(va),
                                              tanha(__high2float(phh)) * sigf(vb));
                )
            } else {
                EPI_LOOP(
                    uint32_t pw = Ph[r * 68 + cp];
                    __half2 phh = *(__half2*)&pw;
                    int tk = stok[r];
                    if (tk >= 0)
                        ((float2*)out)[(size_t)tk * 64 + cp] =
                            make_float2(tanha(__low2float(phh))  * sigf(va),
                                        tanha(__high2float(phh)) * sigf(vb));
                )
            }
        }
        #undef EPI_LOOP
        // no trailing sync needed: next layer's ch0 wait+sync orders Xs2 writes
    }
    #undef STAGE2
    }
    // reset histogram for next launch (graph replay)
    if (blockIdx.x == 0 && threadIdx.x < 9) g_cnt[threadIdx.x] = 0;
}

extern "C" void kernel_launch(void* const* d_in, const int* in_sizes, int n_in,
                              void* d_out, int out_size) {
    const int* pos = (const int*)d_in[0];
    const float* x = (const float*)d_in[1];
    const float* W = (const float*)d_in[2];
    const float* b = (const float*)d_in[3];
    float* out = (float*)d_out;
    (void)in_sizes; (void)n_in; (void)out_size;
    cudaFuncSetAttribute(k_main, cudaFuncAttributeMaxDynamicSharedMemorySize, SMEM_MAIN);
    k_prep_all<<<416, 512>>>(W, pos);
    k_main<<<MAXTILE, 1024, SMEM_MAIN>>>(x, b, out);
}